// round 17
// baseline (speedup 1.0000x reference)
#include <cuda_runtime.h>
#include <cuda_fp16.h>
#include <cstdint>
#include <cstddef>

#define D_MODEL 1024
#define D_FF    4096
#define HEADS   16
#define DKH     64
#define BATCH   2
#define SEQ     2048
#define NTOK    (BATCH*SEQ)
#define D3      (3*D_MODEL)

// ---------------- scratch (device globals; no allocations allowed) ----------
__device__ __half g_h1 [NTOK * D_MODEL];
__device__ __half g_qkv[NTOK * D3];
__device__ __half g_at [NTOK * D_MODEL];
__device__ float  g_x1 [NTOK * D_MODEL];
__device__ __half g_h2 [NTOK * D_MODEL];
__device__ __half g_f1 [NTOK * D_FF];
__device__ __half g_wqkv[D3 * D_MODEL];
__device__ __half g_wo[D_MODEL * D_MODEL];
__device__ __half g_w1[D_FF * D_MODEL];
__device__ __half g_w2[D_MODEL * D_FF];

// ---------------- helpers ---------------------------------------------------
__device__ __forceinline__ uint32_t smem_u32(const void* p) {
    return (uint32_t)__cvta_generic_to_shared(p);
}
#define CP_ASYNC16(dst, src) \
    asm volatile("cp.async.cg.shared.global [%0], [%1], 16;\n" :: "r"(dst), "l"(src))
#define CP_COMMIT() asm volatile("cp.async.commit_group;\n" ::: "memory")
#define CP_WAIT(n)  asm volatile("cp.async.wait_group %0;\n" :: "n"(n) : "memory")

#define MMA_F16(d, a, b) \
    asm volatile("mma.sync.aligned.m16n8k16.row.col.f32.f16.f16.f32 " \
                 "{%0,%1,%2,%3},{%4,%5,%6,%7},{%8,%9},{%0,%1,%2,%3};" \
                 : "+f"(d[0]), "+f"(d[1]), "+f"(d[2]), "+f"(d[3]) \
                 : "r"(a[0]), "r"(a[1]), "r"(a[2]), "r"(a[3]), \
                   "r"(b[0]), "r"(b[1]))

#define LDMX4(r0, r1, r2, r3, addr) \
    asm volatile("ldmatrix.sync.aligned.m8n8.x4.shared.b16 {%0,%1,%2,%3}, [%4];" \
                 : "=r"(r0), "=r"(r1), "=r"(r2), "=r"(r3) : "r"(addr))
#define LDMX4_TRANS(r0, r1, r2, r3, addr) \
    asm volatile("ldmatrix.sync.aligned.m8n8.x4.trans.shared.b16 {%0,%1,%2,%3}, [%4];" \
                 : "=r"(r0), "=r"(r1), "=r"(r2), "=r"(r3) : "r"(addr))

// ---------------- fused prep: weight conversion + LN1 ------------------------
// blocks [0,3072): qkv weights -> fp16
// blocks [3072,12288): W_O/W1/W2 -> fp16
// blocks [12288,16384): LayerNorm of x -> h1 (fp16)
#define PREP_BQ 3072
#define PREP_BR 9216
#define PREP_BL 4096
#define PREP_NB (PREP_BQ + PREP_BR + PREP_BL)

__global__ __launch_bounds__(256) void prep_kernel(
    const float4* __restrict__ Wq, const float4* __restrict__ Wk,
    const float4* __restrict__ Wv, const float4* __restrict__ Wo,
    const float4* __restrict__ W1, const float4* __restrict__ W2,
    const float*  __restrict__ x,  const float* __restrict__ g1,
    const float*  __restrict__ b1,
    __half* __restrict__ wqkv, __half* __restrict__ wo,
    __half* __restrict__ w1,   __half* __restrict__ w2,
    __half* __restrict__ h1)
{
    __shared__ float redS[8], redQ[8];
    __shared__ float bmu, brs;

    const int bid = blockIdx.x;
    const int t = threadIdx.x;

    if (bid < PREP_BQ) {
        const int per = D_MODEL * D_MODEL / 4;
        int i = bid * 256 + t;
        float4 val;
        if (i < per)          val = Wq[i];
        else if (i < 2*per)   val = Wk[i - per];
        else                  val = Wv[i - 2*per];
        __half2* o = (__half2*)(wqkv + (size_t)i * 4);
        o[0] = __floats2half2_rn(val.x, val.y);
        o[1] = __floats2half2_rn(val.z, val.w);
        return;
    }
    if (bid < PREP_BQ + PREP_BR) {
        const int nDD = D_MODEL * D_MODEL / 4;
        const int nDF = D_FF * D_MODEL / 4;
        int i = (bid - PREP_BQ) * 256 + t;
        const float4* src; __half* dst; int j;
        if (i < nDD)           { src = Wo; dst = wo; j = i; }
        else if (i < nDD+nDF)  { src = W1; dst = w1; j = i - nDD; }
        else                   { src = W2; dst = w2; j = i - nDD - nDF; }
        float4 v = src[j];
        __half2* o = (__half2*)(dst + (size_t)j * 4);
        o[0] = __floats2half2_rn(v.x, v.y);
        o[1] = __floats2half2_rn(v.z, v.w);
        return;
    }
    // LayerNorm rows
    {
        const int row = bid - (PREP_BQ + PREP_BR);
        const int lane = t & 31, w = t >> 5;
        const float4* x4 = (const float4*)x + (size_t)row * 256;
        float4 v = x4[t];
        float s  = v.x + v.y + v.z + v.w;
        float s2 = v.x*v.x + v.y*v.y + v.z*v.z + v.w*v.w;
        #pragma unroll
        for (int o = 16; o; o >>= 1) {
            s  += __shfl_xor_sync(0xffffffffu, s, o);
            s2 += __shfl_xor_sync(0xffffffffu, s2, o);
        }
        if (lane == 0) { redS[w] = s; redQ[w] = s2; }
        __syncthreads();
        if (t == 0) {
            float ts = 0.f, tq = 0.f;
            #pragma unroll
            for (int i = 0; i < 8; i++) { ts += redS[i]; tq += redQ[i]; }
            const float mu = ts * (1.f / 1024.f);
            const float var = tq * (1.f / 1024.f) - mu * mu;
            bmu = mu;
            brs = rsqrtf(var + 1e-5f);
        }
        __syncthreads();
        const float mu = bmu, rs = brs;
        float4 gv = ((const float4*)g1)[t];
        float4 bv = ((const float4*)b1)[t];
        __half2* orow = (__half2*)(h1 + (size_t)row * 1024);
        orow[t*2]   = __floats2half2_rn((v.x - mu)*rs*gv.x + bv.x,
                                        (v.y - mu)*rs*gv.y + bv.y);
        orow[t*2+1] = __floats2half2_rn((v.z - mu)*rs*gv.z + bv.z,
                                        (v.w - mu)*rs*gv.w + bv.w);
    }
}

// ---------------- LayerNorm (standalone, for LN2) ----------------------------
__global__ __launch_bounds__(256) void ln_kernel(const float* __restrict__ x,
                                                 const float* __restrict__ g,
                                                 const float* __restrict__ b,
                                                 __half* __restrict__ out)
{
    __shared__ float redS[8], redQ[8];
    __shared__ float bmu, brs;
    const int row = blockIdx.x;
    const int t = threadIdx.x;
    const int lane = t & 31, w = t >> 5;

    const float4* x4 = (const float4*)x + (size_t)row * 256;
    float4 v = x4[t];

    float s  = v.x + v.y + v.z + v.w;
    float s2 = v.x*v.x + v.y*v.y + v.z*v.z + v.w*v.w;
    #pragma unroll
    for (int o = 16; o; o >>= 1) {
        s  += __shfl_xor_sync(0xffffffffu, s, o);
        s2 += __shfl_xor_sync(0xffffffffu, s2, o);
    }
    if (lane == 0) { redS[w] = s; redQ[w] = s2; }
    __syncthreads();
    if (t == 0) {
        float ts = 0.f, tq = 0.f;
        #pragma unroll
        for (int i = 0; i < 8; i++) { ts += redS[i]; tq += redQ[i]; }
        const float mu = ts * (1.f / 1024.f);
        const float var = tq * (1.f / 1024.f) - mu * mu;
        bmu = mu;
        brs = rsqrtf(var + 1e-5f);
    }
    __syncthreads();
    const float mu = bmu, rs = brs;

    float4 gv = ((const float4*)g)[t];
    float4 bv = ((const float4*)b)[t];
    __half2* orow = (__half2*)(out + (size_t)row * 1024);
    orow[t*2]   = __floats2half2_rn((v.x - mu)*rs*gv.x + bv.x,
                                    (v.y - mu)*rs*gv.y + bv.y);
    orow[t*2+1] = __floats2half2_rn((v.z - mu)*rs*gv.z + bv.z,
                                    (v.w - mu)*rs*gv.w + bv.w);
}

// ---------------- FP16 tensor-core GEMM NT (64x128, frag-burst) --------------
// C[N,M] = A[N,K] * B[M,K]^T.  CTA: 64 rows x 128 cols, BK=32, 8 warps in
// 2x4, warp tile 32x32.  3-stage cp.async ring, one sync/k-tile.  All 8
// ldmatrix (both ks halves) burst before the 32 MMAs -> 2x LDSM MLP.
// launch_bounds(256,3): regs cap 85, 3 CTA/SM.
// EPI: 0=none, 1=+bias, 2=+res, 3=relu(+bias)+res.  HOUT: 1 = store half.
#define GLDSH 40                     // 32 + 8 pad halves; 80B rows
#define G_ASTG (64*GLDSH)
#define G_BSTG (128*GLDSH)
#define G_NSTG 3
#define G_SMEM (G_NSTG*(G_ASTG+G_BSTG)*2)    // 46080 bytes

template<int EPI, int HOUT>
__global__ __launch_bounds__(256, 3) void gemm_f16(const __half* __restrict__ A,
                                                   const __half* __restrict__ B,
                                                   void* __restrict__ Cv,
                                                   int N, int M, int K,
                                                   const float* __restrict__ bias,
                                                   const float* __restrict__ res)
{
    extern __shared__ __align__(16) char sh[];
    __half* Ash = (__half*)sh;                     // [3][64][40]
    __half* Bsh = (__half*)sh + G_NSTG * G_ASTG;   // [3][128][40]

    const int t    = threadIdx.x;
    const int lane = t & 31;
    const int warp = t >> 5;
    const int wm   = warp >> 2;
    const int wn   = warp & 3;
    const int g    = lane >> 2;
    const int tig  = lane & 3;
    const int n0   = blockIdx.y * 64;
    const int m0   = blockIdx.x * 128;

    const int a_row = lane & 15;
    const int a_col = (lane >> 4) << 3;
    const int b_row = ((lane >> 4) << 3) + (lane & 7);
    const int b_col = ((lane >> 3) & 1) << 3;

    const int alr = t >> 2;
    const int ach = (t & 3) * 8;
    const __half* Arp  = A + (size_t)(n0 + alr) * K + ach;
    const __half* Brp0 = B + (size_t)(m0 + alr) * K + ach;
    const __half* Brp1 = B + (size_t)(m0 + alr + 64) * K + ach;

    float acc[2][4][4];
    #pragma unroll
    for (int i = 0; i < 2; i++)
        #pragma unroll
        for (int j = 0; j < 4; j++)
            #pragma unroll
            for (int c = 0; c < 4; c++) acc[i][j][c] = 0.f;

    const int nK = K / 32;

    #pragma unroll
    for (int p = 0; p < 2; p++) {
        __half* As = Ash + p * G_ASTG;
        __half* Bs = Bsh + p * G_BSTG;
        const int ko = p * 32;
        CP_ASYNC16(smem_u32(&As[alr * GLDSH + ach]),        Arp + ko);
        CP_ASYNC16(smem_u32(&Bs[alr * GLDSH + ach]),        Brp0 + ko);
        CP_ASYNC16(smem_u32(&Bs[(alr + 64) * GLDSH + ach]), Brp1 + ko);
        CP_COMMIT();
    }

    int cur = 0;
    for (int kt = 0; kt < nK; kt++) {
        if (kt + 1 < nK) CP_WAIT(1); else CP_WAIT(0);
        __syncthreads();

        if (kt + 2 < nK) {
            int p = cur + 2; if (p >= 3) p -= 3;
            const int ko = (kt + 2) * 32;
            __half* As = Ash + p * G_ASTG;
            __half* Bs = Bsh + p * G_BSTG;
            CP_ASYNC16(smem_u32(&As[alr * GLDSH + ach]),        Arp + ko);
            CP_ASYNC16(smem_u32(&Bs[alr * GLDSH + ach]),        Brp0 + ko);
            CP_ASYNC16(smem_u32(&Bs[(alr + 64) * GLDSH + ach]), Brp1 + ko);
            CP_COMMIT();
        }

        const __half* As = Ash + cur * G_ASTG;
        const __half* Bs = Bsh + cur * G_BSTG;

        // burst-load ALL fragments for both ks halves (8 ldmatrix, 2x MLP)
        uint32_t af[2][2][4];
        uint32_t bf[2][4][2];
        #pragma unroll
        for (int ks = 0; ks < 2; ks++) {
            const int kc = ks * 16;
            #pragma unroll
            for (int mt = 0; mt < 2; mt++) {
                const int r = wm * 32 + mt * 16;
                LDMX4(af[ks][mt][0], af[ks][mt][1], af[ks][mt][2], af[ks][mt][3],
                      smem_u32(&As[(r + a_row) * GLDSH + kc + a_col]));
            }
            #pragma unroll
            for (int p = 0; p < 2; p++) {
                const int c = wn * 32 + p * 16;
                uint32_t r0, r1, r2, r3;
                LDMX4(r0, r1, r2, r3,
                      smem_u32(&Bs[(c + b_row) * GLDSH + kc + b_col]));
                bf[ks][2*p][0] = r0;  bf[ks][2*p][1] = r1;
                bf[ks][2*p+1][0] = r2; bf[ks][2*p+1][1] = r3;
            }
        }
        #pragma unroll
        for (int ks = 0; ks < 2; ks++)
            #pragma unroll
            for (int mt = 0; mt < 2; mt++)
                #pragma unroll
                for (int nt = 0; nt < 4; nt++)
                    MMA_F16(acc[mt][nt], af[ks][mt], bf[ks][nt]);

        if (++cur >= 3) cur = 0;
    }

    #pragma unroll
    for (int mt = 0; mt < 2; mt++) {
        const int r0 = n0 + wm * 32 + mt * 16 + g;
        #pragma unroll
        for (int nt = 0; nt < 4; nt++) {
            const int col = m0 + wn * 32 + nt * 8 + 2 * tig;
            float2 v0 = make_float2(acc[mt][nt][0], acc[mt][nt][1]);
            float2 v1 = make_float2(acc[mt][nt][2], acc[mt][nt][3]);
            if (EPI == 1 || EPI == 3) {
                float2 bb = *(const float2*)&bias[col];
                v0.x += bb.x; v0.y += bb.y;
                v1.x += bb.x; v1.y += bb.y;
            }
            if (EPI == 3) {
                v0.x = fmaxf(v0.x, 0.f); v0.y = fmaxf(v0.y, 0.f);
                v1.x = fmaxf(v1.x, 0.f); v1.y = fmaxf(v1.y, 0.f);
            }
            if (EPI == 2 || EPI == 3) {
                float2 r0v = *(const float2*)&res[(size_t)r0 * M + col];
                float2 r1v = *(const float2*)&res[(size_t)(r0 + 8) * M + col];
                v0.x += r0v.x; v0.y += r0v.y;
                v1.x += r1v.x; v1.y += r1v.y;
            }
            if (HOUT) {
                __half* C = (__half*)Cv;
                *(__half2*)&C[(size_t)r0 * M + col]       = __floats2half2_rn(v0.x, v0.y);
                *(__half2*)&C[(size_t)(r0 + 8) * M + col] = __floats2half2_rn(v1.x, v1.y);
            } else {
                float* C = (float*)Cv;
                *(float2*)&C[(size_t)r0 * M + col]       = v0;
                *(float2*)&C[(size_t)(r0 + 8) * M + col] = v1;
            }
        }
    }
}

// ---------------- FP16 flash attention (R16, proven) -------------------------
#define KSTG 4608
#define HQS  0
#define HKS  9216
#define HVS  (9216 + 3*KSTG)
#define HPS  (HVS + 3*KSTG)
#define HTOT (HPS + 9216)
#define AMSK_B (HTOT*2)
#define ASMEM_BYTES (AMSK_B + 3*64*4)

__global__ __launch_bounds__(256) void attn_tc(const __half* __restrict__ QKV,
                                               const unsigned char* __restrict__ mask,
                                               __half* __restrict__ O)
{
    extern __shared__ char shb[];
    __half* Qs  = (__half*)shb + HQS;
    __half* Ks  = (__half*)shb + HKS;
    __half* Vs  = (__half*)shb + HVS;
    __half* Ps  = (__half*)shb + HPS;
    float*  msk = (float*)(shb + AMSK_B);

    const int t    = threadIdx.x;
    const int lane = t & 31;
    const int warp = t >> 5;
    const int g    = lane >> 2;
    const int tig  = lane & 3;
    const int q0   = blockIdx.x * 128;
    const int h    = blockIdx.y;
    const int b    = blockIdx.z;
    const size_t baseQ = (size_t)b * SEQ * D3 + (size_t)h * DKH;
    const size_t baseK = baseQ + D_MODEL;
    const size_t baseV = baseQ + 2 * D_MODEL;
    const size_t baseO = (size_t)b * SEQ * D_MODEL + (size_t)h * DKH;
    const int rA = warp * 16 + g;

    const int a_row = lane & 15;
    const int a_col = (lane >> 4) << 3;
    const int b_row = ((lane >> 4) << 3) + (lane & 7);
    const int b_col = ((lane >> 3) & 1) << 3;

    #pragma unroll
    for (int i = 0; i < 4; i++) {
        int idx = t + i * 256, row = idx >> 3, s8 = (idx & 7) * 8;
        CP_ASYNC16(smem_u32(&Qs[row * 72 + s8]),
                   &QKV[baseQ + (size_t)(q0 + row) * D3 + s8]);
    }
    #pragma unroll
    for (int i = 0; i < 2; i++) {
        int idx = t + i * 256, row = idx >> 3, s8 = (idx & 7) * 8;
        CP_ASYNC16(smem_u32(&Ks[row * 72 + s8]),
                   &QKV[baseK + (size_t)row * D3 + s8]);
        CP_ASYNC16(smem_u32(&Vs[row * 72 + s8]),
                   &QKV[baseV + (size_t)row * D3 + s8]);
    }
    CP_COMMIT();
    #pragma unroll
    for (int i = 0; i < 2; i++) {
        int idx = t + i * 256, row = idx >> 3, s8 = (idx & 7) * 8;
        CP_ASYNC16(smem_u32(&Ks[KSTG + row * 72 + s8]),
                   &QKV[baseK + (size_t)(64 + row) * D3 + s8]);
        CP_ASYNC16(smem_u32(&Vs[KSTG + row * 72 + s8]),
                   &QKV[baseV + (size_t)(64 + row) * D3 + s8]);
    }
    CP_COMMIT();
    if (t < 64) {
        msk[t]      = mask[(size_t)b * SEQ + t]      ? -3.0e38f : 0.f;
        msk[64 + t] = mask[(size_t)b * SEQ + 64 + t] ? -3.0e38f : 0.f;
    }

    float m0 = -3.0e38f, m1 = -3.0e38f, l0 = 0.f, l1 = 0.f;
    float oacc[8][4];
    #pragma unroll
    for (int nt = 0; nt < 8; nt++)
        #pragma unroll
        for (int c = 0; c < 4; c++) oacc[nt][c] = 0.f;

    uint32_t qf[4][4];
    const int ntiles = SEQ / 64;
    int cur = 0;
    for (int kt = 0; kt < ntiles; kt++) {
        if (kt + 1 < ntiles) CP_WAIT(1); else CP_WAIT(0);
        __syncthreads();

        if (kt == 0) {
            #pragma unroll
            for (int kc4 = 0; kc4 < 4; kc4++)
                LDMX4(qf[kc4][0], qf[kc4][1], qf[kc4][2], qf[kc4][3],
                      smem_u32(&Qs[(warp * 16 + a_row) * 72 + kc4 * 16 + a_col]));
        }

        if (kt + 2 < ntiles) {
            int p = cur + 2; if (p >= 3) p -= 3;
            const int k0n = (kt + 2) * 64;
            #pragma unroll
            for (int i = 0; i < 2; i++) {
                int idx = t + i * 256, row = idx >> 3, s8 = (idx & 7) * 8;
                CP_ASYNC16(smem_u32(&Ks[p * KSTG + row * 72 + s8]),
                           &QKV[baseK + (size_t)(k0n + row) * D3 + s8]);
                CP_ASYNC16(smem_u32(&Vs[p * KSTG + row * 72 + s8]),
                           &QKV[baseV + (size_t)(k0n + row) * D3 + s8]);
            }
            CP_COMMIT();
            if (t < 64) msk[p * 64 + t] =
                mask[(size_t)b * SEQ + k0n + t] ? -3.0e38f : 0.f;
        }

        const __half* Kc = Ks + cur * KSTG;
        const __half* Vc = Vs + cur * KSTG;
        const float*  mc = msk + cur * 64;

        float sc[8][4];
        #pragma unroll
        for (int nt = 0; nt < 8; nt++)
            #pragma unroll
            for (int c = 0; c < 4; c++) sc[nt][c] = 0.f;

        #pragma unroll
        for (int kc4 = 0; kc4 < 4; kc4++) {
            const int kc = kc4 * 16;
            #pragma unroll
            for (int p = 0; p < 4; p++) {
                const int c = p * 16;
                uint32_t r0, r1, r2, r3;
                LDMX4(r0, r1, r2, r3,
                      smem_u32(&Kc[(c + b_row) * 72 + kc + b_col]));
                uint32_t b0[2] = {r0, r1};
                uint32_t b1[2] = {r2, r3};
                MMA_F16(sc[2*p],     qf[kc4], b0);
                MMA_F16(sc[2*p + 1], qf[kc4], b1);
            }
        }

        float tm0 = -3.0e38f, tm1 = -3.0e38f;
        #pragma unroll
        for (int nt = 0; nt < 8; nt++) {
            const float mk0 = mc[nt * 8 + 2 * tig];
            const float mk1 = mc[nt * 8 + 2 * tig + 1];
            sc[nt][0] = sc[nt][0] * 0.125f + mk0;
            sc[nt][1] = sc[nt][1] * 0.125f + mk1;
            sc[nt][2] = sc[nt][2] * 0.125f + mk0;
            sc[nt][3] = sc[nt][3] * 0.125f + mk1;
            tm0 = fmaxf(tm0, fmaxf(sc[nt][0], sc[nt][1]));
            tm1 = fmaxf(tm1, fmaxf(sc[nt][2], sc[nt][3]));
        }
        tm0 = fmaxf(tm0, __shfl_xor_sync(0xffffffffu, tm0, 1));
        tm0 = fmaxf(tm0, __shfl_xor_sync(0xffffffffu, tm0, 2));
        tm1 = fmaxf(tm1, __shfl_xor_sync(0xffffffffu, tm1, 1));
        tm1 = fmaxf(tm1, __shfl_xor_sync(0xffffffffu, tm1, 2));

        const float nm0 = fmaxf(m0, tm0), nm1 = fmaxf(m1, tm1);
        const float a0 = __expf(m0 - nm0), a1 = __expf(m1 - nm1);

        float ps0 = 0.f, ps1 = 0.f;
        #pragma unroll
        for (int nt = 0; nt < 8; nt++) {
            const float p0 = __expf(sc[nt][0] - nm0);
            const float p1 = __expf(sc[nt][1] - nm0);
            const float p2 = __expf(sc[nt][2] - nm1);
            const float p3 = __expf(sc[nt][3] - nm1);
            ps0 += p0 + p1; ps1 += p2 + p3;
            *(__half2*)&Ps[rA * 72 + nt * 8 + 2*tig]       = __floats2half2_rn(p0, p1);
            *(__half2*)&Ps[(rA + 8) * 72 + nt * 8 + 2*tig] = __floats2half2_rn(p2, p3);
        }
        ps0 += __shfl_xor_sync(0xffffffffu, ps0, 1);
        ps0 += __shfl_xor_sync(0xffffffffu, ps0, 2);
        ps1 += __shfl_xor_sync(0xffffffffu, ps1, 1);
        ps1 += __shfl_xor_sync(0xffffffffu, ps1, 2);

        l0 = l0 * a0 + ps0;  l1 = l1 * a1 + ps1;
        m0 = nm0;  m1 = nm1;
        #pragma unroll
        for (int nt = 0; nt < 8; nt++) {
            oacc[nt][0] *= a0; oacc[nt][1] *= a0;
            oacc[nt][2] *= a1; oacc[nt][3] *= a1;
        }
        __syncwarp();

        const int mi = lane >> 3, rr = lane & 7;
        #pragma unroll
        for (int kc4 = 0; kc4 < 4; kc4++) {
            const int kc = kc4 * 16;
            uint32_t af[4];
            LDMX4(af[0], af[1], af[2], af[3],
                  smem_u32(&Ps[(warp * 16 + a_row) * 72 + kc + a_col]));
            #pragma unroll
            for (int ntp = 0; ntp < 4; ntp++) {
                const int key = kc + ((mi & 1) << 3) + rr;
                const int dim = ntp * 16 + ((mi >> 1) << 3);
                uint32_t r0, r1, r2, r3;
                LDMX4_TRANS(r0, r1, r2, r3, smem_u32(&Vc[key * 72 + dim]));
                uint32_t b0[2] = {r0, r1};
                uint32_t b1[2] = {r2, r3};
                MMA_F16(oacc[2*ntp],     af, b0);
                MMA_F16(oacc[2*ntp + 1], af, b1);
            }
        }
        if (++cur >= 3) cur = 0;
    }

    const float i0 = 1.f / l0, i1 = 1.f / l1;
    #pragma unroll
    for (int nt = 0; nt < 8; nt++) {
        const int col = nt * 8 + 2 * tig;
        *(__half2*)&O[baseO + (size_t)(q0 + rA) * D_MODEL + col] =
            __floats2half2_rn(oacc[nt][0] * i0, oacc[nt][1] * i0);
        *(__half2*)&O[baseO + (size_t)(q0 + rA + 8) * D_MODEL + col] =
            __floats2half2_rn(oacc[nt][2] * i1, oacc[nt][3] * i1);
    }
}

// ---------------- launch ---------------------------------------------------
extern "C" void kernel_launch(void* const* d_in, const int* in_sizes, int n_in,
                              void* d_out, int out_size)
{
    const float* x     = (const float*)d_in[0];
    const unsigned char* mask = (const unsigned char*)d_in[1];
    const float* W_Q   = (const float*)d_in[2];
    const float* W_K   = (const float*)d_in[3];
    const float* W_V   = (const float*)d_in[4];
    const float* W_O   = (const float*)d_in[5];
    const float* W1    = (const float*)d_in[6];
    const float* b1    = (const float*)d_in[7];
    const float* W2    = (const float*)d_in[8];
    const float* b2    = (const float*)d_in[9];
    const float* g1    = (const float*)d_in[10];
    const float* beta1 = (const float*)d_in[11];
    const float* g2    = (const float*)d_in[12];
    const float* beta2 = (const float*)d_in[13];
    float* out = (float*)d_out;

    __half *h1, *qkv, *at, *h2, *f1;
    __half *wqkv, *wo, *w1, *w2;
    float *x1;
    cudaGetSymbolAddress((void**)&h1,   g_h1);
    cudaGetSymbolAddress((void**)&qkv,  g_qkv);
    cudaGetSymbolAddress((void**)&at,   g_at);
    cudaGetSymbolAddress((void**)&x1,   g_x1);
    cudaGetSymbolAddress((void**)&h2,   g_h2);
    cudaGetSymbolAddress((void**)&f1,   g_f1);
    cudaGetSymbolAddress((void**)&wqkv, g_wqkv);
    cudaGetSymbolAddress((void**)&wo,   g_wo);
    cudaGetSymbolAddress((void**)&w1,   g_w1);
    cudaGetSymbolAddress((void**)&w2,   g_w2);

    cudaFuncSetAttribute(attn_tc, cudaFuncAttributeMaxDynamicSharedMemorySize,
                         ASMEM_BYTES);
    cudaFuncSetAttribute(gemm_f16<0,1>, cudaFuncAttributeMaxDynamicSharedMemorySize, G_SMEM);
    cudaFuncSetAttribute(gemm_f16<2,0>, cudaFuncAttributeMaxDynamicSharedMemorySize, G_SMEM);
    cudaFuncSetAttribute(gemm_f16<1,1>, cudaFuncAttributeMaxDynamicSharedMemorySize, G_SMEM);
    cudaFuncSetAttribute(gemm_f16<3,0>, cudaFuncAttributeMaxDynamicSharedMemorySize, G_SMEM);

    const dim3 gQKV(D3/128,      NTOK/64);   // (24, 64)
    const dim3 gDD (D_MODEL/128, NTOK/64);   // (8, 64)
    const dim3 gDF (D_FF/128,    NTOK/64);   // (32, 64)

    // 0+1. fused prep: weight conversion + LN1 (one launch)
    prep_kernel<<<PREP_NB, 256>>>((const float4*)W_Q, (const float4*)W_K,
                                  (const float4*)W_V, (const float4*)W_O,
                                  (const float4*)W1,  (const float4*)W2,
                                  x, g1, beta1,
                                  wqkv, wo, w1, w2, h1);
    // 2. fused QKV projection
    gemm_f16<0,1><<<gQKV, 256, G_SMEM>>>(h1, wqkv, qkv, NTOK, D3, D_MODEL, nullptr, nullptr);
    // 3. flash attention
    attn_tc<<<dim3(SEQ/128, HEADS, BATCH), 256, ASMEM_BYTES>>>(qkv, mask, at);
    // 4. output projection + residual (fp32 out)
    gemm_f16<2,0><<<gDD, 256, G_SMEM>>>(at, wo, x1, NTOK, D_MODEL, D_MODEL, nullptr, x);
    // 5. second LN
    ln_kernel<<<NTOK, 256>>>(x1, g2, beta2, h2);
    // 6. FFN1 (+b1)
    gemm_f16<1,1><<<gDF, 256, G_SMEM>>>(h2, w1, f1, NTOK, D_FF, D_MODEL, b1, nullptr);
    // 7. FFN2: relu(C + b2) + residual(x1), fp32 final
    gemm_f16<3,0><<<gDD, 256, G_SMEM>>>(f1, w2, out, NTOK, D_MODEL, D_FF, b2, x1);
}